// round 11
// baseline (speedup 1.0000x reference)
#include <cuda_runtime.h>
#include <cuda_bf16.h>

// Problem constants
#define NB    4
#define NC    2000      // curves per batch
#define NLS   2000      // line samples per batch
#define NS    4000      // surfaces per batch
#define NF    8000      // faces per batch
#define NTS   26000     // triangle samples per batch
#define NPT   (NC + NLS + NS + NTS)   // 34000 points per batch
#define NPTOT (NB * NPT)              // 136000 points total
#define OG    258       // occ grid edge (256 + 2*2 pad - 3 + 1)
#define OGSQ  (OG * OG)                        // 66564
#define X_ELEMS   (NB * NPT * 3)               // 408000
#define OCC_PER_B ((long)OG * OGSQ)            // 17,173,512 (divisible by 4)
#define OCC_ELEMS (NB * OCC_PER_B)             // 68,669,448

#define ZBLK   1184                 // zero-job blocks (148 SMs x 8)
#define PTBLK  ((NPTOT + 255) / 256)            // 532 points-job blocks
#define SCTHREADS (9 * NPT)                     // 306000
#define SCBLK  ((SCTHREADS + 255) / 256)        // 1196 scatter-job blocks

// Scratch: packed voxel coords per point (c0 | c1<<8 | c2<<16).
__device__ int g_coords[NPTOT];

__device__ __forceinline__ int cube_coord(float p) {
    float t = __fadd_rn(__fmul_rn(p, 256.0f), 128.5f);
    t = fminf(255.0f, fmaxf(0.0f, t));
    return (int)t;   // t >= 0 so truncation == floor
}

// ---------------------------------------------------------------------------
// points job: one thread per point. Exact f32 op order of the reference
// (no FMA contraction). Writes x and the packed voxel coord.
// ---------------------------------------------------------------------------
__device__ __forceinline__ void points_job(int idx,
                              const float* __restrict__ curves,
                              const float* __restrict__ surfaces,
                              const float* __restrict__ t_line,
                              const float* __restrict__ uv,
                              const int*   __restrict__ lines_array,
                              const int*   __restrict__ faces_array,
                              const int*   __restrict__ line_choice,
                              const int*   __restrict__ tri_choice,
                              float* __restrict__ out) {
    int b = idx / NPT;
    int j = idx - b * NPT;

    float p0, p1, p2;

    if (j < NC) {
        const float* c = curves + ((long)(b * NC + j)) * 3;
        p0 = c[0]; p1 = c[1]; p2 = c[2];
    } else if (j < NC + NLS) {
        int jj = j - NC;
        int lc = line_choice[b * NLS + jj];
        int s0 = lines_array[((long)(b * NC + lc)) * 2 + 0];
        int s1 = lines_array[((long)(b * NC + lc)) * 2 + 1];
        const float* A  = curves + ((long)(b * NC + s0)) * 3;
        const float* Bp = curves + ((long)(b * NC + s1)) * 3;
        float t = t_line[b * NLS + jj];
        p0 = __fadd_rn(A[0], __fmul_rn(t, __fsub_rn(Bp[0], A[0])));
        p1 = __fadd_rn(A[1], __fmul_rn(t, __fsub_rn(Bp[1], A[1])));
        p2 = __fadd_rn(A[2], __fmul_rn(t, __fsub_rn(Bp[2], A[2])));
    } else if (j < NC + NLS + NS) {
        int jj = j - (NC + NLS);
        const float* s = surfaces + ((long)(b * NS + jj)) * 3;
        p0 = s[0]; p1 = s[1]; p2 = s[2];
    } else {
        int jj = j - (NC + NLS + NS);
        int tc = tri_choice[b * NTS + jj];
        const int* f = faces_array + ((long)(b * NF + tc)) * 3;
        const float* ta  = surfaces + ((long)(b * NS + f[0])) * 3;
        const float* tb  = surfaces + ((long)(b * NS + f[1])) * 3;
        const float* tcx = surfaces + ((long)(b * NS + f[2])) * 3;
        float u = uv[((long)(b * NTS + jj)) * 2 + 0];
        float v = uv[((long)(b * NTS + jj)) * 2 + 1];
        if (__fadd_rn(u, v) > 1.0f) {
            u = __fsub_rn(1.0f, u);
            v = __fsub_rn(1.0f, v);
        }
        // (ta + u*(tb-ta)) + v*(tc-ta), exact reference op order
        p0 = __fadd_rn(__fadd_rn(ta[0], __fmul_rn(u, __fsub_rn(tb[0], ta[0]))),
                       __fmul_rn(v, __fsub_rn(tcx[0], ta[0])));
        p1 = __fadd_rn(__fadd_rn(ta[1], __fmul_rn(u, __fsub_rn(tb[1], ta[1]))),
                       __fmul_rn(v, __fsub_rn(tcx[1], ta[1])));
        p2 = __fadd_rn(__fadd_rn(ta[2], __fmul_rn(u, __fsub_rn(tb[2], ta[2]))),
                       __fmul_rn(v, __fsub_rn(tcx[2], ta[2])));
    }

    float* xo = out + ((long)idx) * 3;
    xo[0] = p0; xo[1] = p1; xo[2] = p2;

    int c0 = cube_coord(p0);
    int c1 = cube_coord(p1);
    int c2 = cube_coord(p2);
    g_coords[idx] = c0 | (c1 << 8) | (c2 << 16);
}

// ---------------------------------------------------------------------------
// Fused kernel. Block ranges:
//   [0, nzero)        : grid-stride zero of slab `bzero` (~14 float4/thread)
//   [nzero, gridDim)  : tail job — points (mode 0) or scatter of slab
//                       `bscatter` (mode 1), one thread per (point, d0, d1)
//                       row of the dilated 3x3x3 block.
// Jobs in one launch touch disjoint memory (different slabs / x / coords),
// so the latency-bound tail job hides inside the zero sweep's bandwidth
// shadow. Scatter of slab b runs the launch AFTER slab b's zero, so its
// stores hit L2-dirty lines (dilation == padded 3-maxpool of the one-hot
// grid; coords always in-bounds; writes idempotent 1.0f -> no races).
// ---------------------------------------------------------------------------
__global__ void fused_kernel(float* __restrict__ out,
                             int nzero, int bzero, int mode, int bscatter,
                             const float* __restrict__ curves,
                             const float* __restrict__ surfaces,
                             const float* __restrict__ t_line,
                             const float* __restrict__ uv,
                             const int*   __restrict__ lines_array,
                             const int*   __restrict__ faces_array,
                             const int*   __restrict__ line_choice,
                             const int*   __restrict__ tri_choice) {
    if ((int)blockIdx.x < nzero) {
        // zero job: grid-stride float4 sweep of slab bzero
        float4* p4 = (float4*)(out + X_ELEMS + (long)bzero * OCC_PER_B);
        const int n4 = (int)(OCC_PER_B / 4);        // 4,293,378
        int stride = nzero * blockDim.x;
        const float4 z = make_float4(0.f, 0.f, 0.f, 0.f);
        for (int i = blockIdx.x * blockDim.x + threadIdx.x; i < n4; i += stride)
            p4[i] = z;
        return;
    }

    int t = (blockIdx.x - nzero) * blockDim.x + threadIdx.x;

    if (mode == 0) {
        // points job
        if (t < NPTOT)
            points_job(t, curves, surfaces, t_line, uv,
                       lines_array, faces_array, line_choice, tri_choice, out);
    } else {
        // scatter job for slab bscatter
        if (t < SCTHREADS) {
            int r = t / NPT;                // 0..8
            int pidx = t - r * NPT;
            int d0 = r / 3;
            int d1 = r - d0 * 3;
            int packed = g_coords[bscatter * NPT + pidx];   // coalesced
            int c0 = packed & 0xFF;
            int c1 = (packed >> 8) & 0xFF;
            int c2 = (packed >> 16) & 0xFF;
            float* row = out + X_ELEMS + (long)bscatter * OCC_PER_B
                       + (long)(c0 + d0) * OGSQ + (long)(c1 + d1) * OG + c2;
            row[0] = 1.0f; row[1] = 1.0f; row[2] = 1.0f;
        }
    }
}

extern "C" void kernel_launch(void* const* d_in, const int* in_sizes, int n_in,
                              void* d_out, int out_size) {
    // metadata order:
    // 0 imgs (unused), 1 curves, 2 surfaces, 3 t_line, 4 uv,
    // 5 lines_array, 6 faces_array, 7 indices_array (unused),
    // 8 line_choice, 9 tri_choice
    const float* curves      = (const float*)d_in[1];
    const float* surfaces    = (const float*)d_in[2];
    const float* t_line      = (const float*)d_in[3];
    const float* uv          = (const float*)d_in[4];
    const int*   lines_array = (const int*)d_in[5];
    const int*   faces_array = (const int*)d_in[6];
    const int*   line_choice = (const int*)d_in[8];
    const int*   tri_choice  = (const int*)d_in[9];
    float* out = (float*)d_out;

    // k0: zero slab 0  || points
    fused_kernel<<<ZBLK + PTBLK, 256>>>(out, ZBLK, 0, /*mode=*/0, -1,
                                        curves, surfaces, t_line, uv,
                                        lines_array, faces_array,
                                        line_choice, tri_choice);
    // k1..k3: zero slab b || scatter slab b-1
    for (int b = 1; b < NB; b++) {
        fused_kernel<<<ZBLK + SCBLK, 256>>>(out, ZBLK, b, /*mode=*/1, b - 1,
                                            curves, surfaces, t_line, uv,
                                            lines_array, faces_array,
                                            line_choice, tri_choice);
    }
    // k4: scatter slab 3 only (no zero range)
    fused_kernel<<<SCBLK, 256>>>(out, 0, 0, /*mode=*/1, NB - 1,
                                 curves, surfaces, t_line, uv,
                                 lines_array, faces_array,
                                 line_choice, tri_choice);
}

// round 12
// speedup vs baseline: 1.0035x; 1.0035x over previous
#include <cuda_runtime.h>
#include <cuda_bf16.h>

// Problem constants
#define NB    4
#define NC    2000      // curves per batch
#define NLS   2000      // line samples per batch
#define NS    4000      // surfaces per batch
#define NF    8000      // faces per batch
#define NTS   26000     // triangle samples per batch
#define NPT   (NC + NLS + NS + NTS)   // 34000 points per batch
#define NPTOT (NB * NPT)              // 136000 points total
#define OG    258       // occ grid edge (256 + 2*2 pad - 3 + 1)
#define OGSQ  (OG * OG)                        // 66564
#define X_ELEMS   (NB * NPT * 3)               // 408000
#define OCC_PER_B 17173512L                    // OG^3, divisible by 4 and 8
#define OCC_ELEMS (NB * OCC_PER_B)             // 68,669,448

// Bitmap: 1 bit per voxel, per batch. Words per batch (padded to word):
#define WPB   536673                           // ceil(OCC_PER_B / 32)
#define NW    (NB * WPB)                       // 2,146,692 (divisible by 4)

// 16B-aligned bitmap scratch (aliased as uint32 in kernels).
__device__ uint4 g_bitmap4[NW / 4];            // 536,673 uint4 = 8.59 MB

// ---------------------------------------------------------------------------
// Kernel 0: clear the bitmap (8.6 MB, dense uint4 stores).
// ---------------------------------------------------------------------------
__global__ void bitmap_zero_kernel() {
    int i = blockIdx.x * blockDim.x + threadIdx.x;
    if (i < NW / 4) g_bitmap4[i] = make_uint4(0u, 0u, 0u, 0u);
}

// ---------------------------------------------------------------------------
// Kernel 1: one thread per point. Computes the point with the exact f32 op
// order of the reference (no FMA contraction), writes x, and sets the 27
// dilated occupancy bits (3x3 rows of 3 consecutive bits) via atomicOr.
// Dilation == padded 3-maxpool of the one-hot grid; coords always in-bounds
// (c in [0,255] -> voxel coords in [0,257]).
// ---------------------------------------------------------------------------
__device__ __forceinline__ int cube_coord(float p) {
    float t = __fadd_rn(__fmul_rn(p, 256.0f), 128.5f);
    t = fminf(255.0f, fmaxf(0.0f, t));
    return (int)t;   // t >= 0 so truncation == floor
}

__global__ void points_kernel(const float* __restrict__ curves,
                              const float* __restrict__ surfaces,
                              const float* __restrict__ t_line,
                              const float* __restrict__ uv,
                              const int*   __restrict__ lines_array,
                              const int*   __restrict__ faces_array,
                              const int*   __restrict__ line_choice,
                              const int*   __restrict__ tri_choice,
                              float* __restrict__ out) {
    int idx = blockIdx.x * blockDim.x + threadIdx.x;
    if (idx >= NPTOT) return;
    int b = idx / NPT;
    int j = idx - b * NPT;

    float p0, p1, p2;

    if (j < NC) {
        // segment 0: curves passthrough
        const float* c = curves + ((long)(b * NC + j)) * 3;
        p0 = c[0]; p1 = c[1]; p2 = c[2];
    } else if (j < NC + NLS) {
        // segment 1: line interpolation  a + t*(b-a)
        int jj = j - NC;
        int lc = line_choice[b * NLS + jj];
        int s0 = lines_array[((long)(b * NC + lc)) * 2 + 0];
        int s1 = lines_array[((long)(b * NC + lc)) * 2 + 1];
        const float* A  = curves + ((long)(b * NC + s0)) * 3;
        const float* Bp = curves + ((long)(b * NC + s1)) * 3;
        float t = t_line[b * NLS + jj];
        p0 = __fadd_rn(A[0], __fmul_rn(t, __fsub_rn(Bp[0], A[0])));
        p1 = __fadd_rn(A[1], __fmul_rn(t, __fsub_rn(Bp[1], A[1])));
        p2 = __fadd_rn(A[2], __fmul_rn(t, __fsub_rn(Bp[2], A[2])));
    } else if (j < NC + NLS + NS) {
        // segment 2: surfaces passthrough
        int jj = j - (NC + NLS);
        const float* s = surfaces + ((long)(b * NS + jj)) * 3;
        p0 = s[0]; p1 = s[1]; p2 = s[2];
    } else {
        // segment 3: triangle barycentric sample
        int jj = j - (NC + NLS + NS);
        int tc = tri_choice[b * NTS + jj];
        const int* f = faces_array + ((long)(b * NF + tc)) * 3;
        const float* ta  = surfaces + ((long)(b * NS + f[0])) * 3;
        const float* tb  = surfaces + ((long)(b * NS + f[1])) * 3;
        const float* tcx = surfaces + ((long)(b * NS + f[2])) * 3;
        float u = uv[((long)(b * NTS + jj)) * 2 + 0];
        float v = uv[((long)(b * NTS + jj)) * 2 + 1];
        if (__fadd_rn(u, v) > 1.0f) {
            u = __fsub_rn(1.0f, u);
            v = __fsub_rn(1.0f, v);
        }
        // (ta + u*(tb-ta)) + v*(tc-ta), exact reference op order
        p0 = __fadd_rn(__fadd_rn(ta[0], __fmul_rn(u, __fsub_rn(tb[0], ta[0]))),
                       __fmul_rn(v, __fsub_rn(tcx[0], ta[0])));
        p1 = __fadd_rn(__fadd_rn(ta[1], __fmul_rn(u, __fsub_rn(tb[1], ta[1]))),
                       __fmul_rn(v, __fsub_rn(tcx[1], ta[1])));
        p2 = __fadd_rn(__fadd_rn(ta[2], __fmul_rn(u, __fsub_rn(tb[2], ta[2]))),
                       __fmul_rn(v, __fsub_rn(tcx[2], ta[2])));
    }

    // write x
    float* xo = out + ((long)idx) * 3;
    xo[0] = p0; xo[1] = p1; xo[2] = p2;

    // set 27 dilated bits: 9 rows of 3 consecutive bits
    int c0 = cube_coord(p0);
    int c1 = cube_coord(p1);
    int c2 = cube_coord(p2);
    unsigned int* bm = (unsigned int*)g_bitmap4 + b * WPB;
    #pragma unroll
    for (int d0 = 0; d0 < 3; d0++) {
        long base0 = (long)(c0 + d0) * OGSQ;
        #pragma unroll
        for (int d1 = 0; d1 < 3; d1++) {
            long p = base0 + (long)(c1 + d1) * OG + c2;   // first of 3 bits
            int w = (int)(p >> 5);
            int s = (int)(p & 31);
            atomicOr(&bm[w], 7u << s);                    // in-word part
            if (s > 29)                                   // spill into next word
                atomicOr(&bm[w + 1], 7u >> (32 - s));
        }
    }
}

// ---------------------------------------------------------------------------
// Kernel 2: dense sweep. One thread per bitmap word: read 32 occupancy bits
// (coalesced, L2-resident), write 32 voxels = 8 float4 of 0.0/1.0. The whole
// 274 MB output is written exactly once, fully dense, with nothing else
// running -> full streaming-write bandwidth. Batch boundary is float4-
// aligned (OCC_PER_B % 4 == 0); only the final word per batch is partial.
// ---------------------------------------------------------------------------
__global__ void sweep_kernel(float* __restrict__ out) {
    int t = blockIdx.x * blockDim.x + threadIdx.x;
    if (t >= NW) return;
    int b = t / WPB;
    int w = t - b * WPB;

    unsigned int bits = ((const unsigned int*)g_bitmap4)[t];

    float* occ = out + X_ELEMS + (long)b * OCC_PER_B;
    long v0 = (long)w * 32;                 // first voxel of this word

    #pragma unroll
    for (int k = 0; k < 8; k++) {
        long v = v0 + k * 4;
        if (v + 3 < OCC_PER_B) {            // boundary is float4-aligned
            float4 q;
            q.x = (bits >> (k * 4 + 0)) & 1u ? 1.0f : 0.0f;
            q.y = (bits >> (k * 4 + 1)) & 1u ? 1.0f : 0.0f;
            q.z = (bits >> (k * 4 + 2)) & 1u ? 1.0f : 0.0f;
            q.w = (bits >> (k * 4 + 3)) & 1u ? 1.0f : 0.0f;
            *(float4*)(occ + v) = q;
        }
    }
}

extern "C" void kernel_launch(void* const* d_in, const int* in_sizes, int n_in,
                              void* d_out, int out_size) {
    // metadata order:
    // 0 imgs (unused), 1 curves, 2 surfaces, 3 t_line, 4 uv,
    // 5 lines_array, 6 faces_array, 7 indices_array (unused),
    // 8 line_choice, 9 tri_choice
    const float* curves      = (const float*)d_in[1];
    const float* surfaces    = (const float*)d_in[2];
    const float* t_line      = (const float*)d_in[3];
    const float* uv          = (const float*)d_in[4];
    const int*   lines_array = (const int*)d_in[5];
    const int*   faces_array = (const int*)d_in[6];
    const int*   line_choice = (const int*)d_in[8];
    const int*   tri_choice  = (const int*)d_in[9];
    float* out = (float*)d_out;

    // k0: clear bitmap (8.6 MB)
    int bz = (NW / 4 + 255) / 256;
    bitmap_zero_kernel<<<bz, 256>>>();

    // k1: points + bit scatter
    int pb = (NPTOT + 255) / 256;
    points_kernel<<<pb, 256>>>(curves, surfaces, t_line, uv,
                               lines_array, faces_array,
                               line_choice, tri_choice, out);

    // k2: dense 274 MB sweep from bitmap
    int sw = (NW + 255) / 256;
    sweep_kernel<<<sw, 256>>>(out);
}